// round 10
// baseline (speedup 1.0000x reference)
#include <cuda_runtime.h>
#include <cuda_fp16.h>
#include <stdint.h>

// Problem constants
#define B_   4
#define N_   2048
#define C_   256
#define H_   16
#define D_   16
#define BH_  (B_ * H_)          // 64
#define M_   (B_ * N_)          // 8192
#define K3_  (3 * C_)           // 768

#define L2E 1.4426950408889634f

// ---------------------------------------------------------------------------
// Scratch (device globals — no allocations allowed)
// ---------------------------------------------------------------------------
__device__ __align__(128) __half g_xh[M_ * C_],  g_xl[M_ * C_];      // x hi/lo [M][C]
__device__ __align__(128) __half g_wqt_h[K3_ * C_], g_wqt_l[K3_ * C_]; // w_qkv^T [768][256]
__device__ __align__(128) __half g_wpt_h[C_ * C_],  g_wpt_l[C_ * C_];  // w_proj^T [256][256]

__device__ __align__(128) __half g_qhi[BH_ * N_ * D_], g_qlo[BH_ * N_ * D_]; // [bh][n][d]
__device__ __align__(128) __half g_khi[BH_ * N_ * D_], g_klo[BH_ * N_ * D_];
__device__ __align__(128) __half g_vthi[BH_ * D_ * N_];               // [bh][d][n] (fp16 only)

__device__ __align__(128) __half g_atth[M_ * C_], g_attl[M_ * C_];   // attn out hi/lo [M][C]

// ---------------------------------------------------------------------------
// helpers
// ---------------------------------------------------------------------------
__device__ __forceinline__ void mma16816(float* c, const uint32_t* a,
                                         uint32_t b0, uint32_t b1)
{
    asm volatile(
        "mma.sync.aligned.m16n8k16.row.col.f32.f16.f16.f32 "
        "{%0,%1,%2,%3}, {%4,%5,%6,%7}, {%8,%9}, {%0,%1,%2,%3};"
        : "+f"(c[0]), "+f"(c[1]), "+f"(c[2]), "+f"(c[3])
        : "r"(a[0]), "r"(a[1]), "r"(a[2]), "r"(a[3]), "r"(b0), "r"(b1));
}

__device__ __forceinline__ uint32_t packf16(float lo, float hi)
{
    uint32_t r;
    asm("cvt.rn.f16x2.f32 %0, %1, %2;" : "=r"(r) : "f"(hi), "f"(lo));
    return r;
}

__device__ __forceinline__ uint32_t ex2_f16x2(uint32_t a)
{
    uint32_t r;
    asm("ex2.approx.f16x2 %0, %1;" : "=r"(r) : "r"(a));
    return r;
}

__device__ __forceinline__ float ex2(float x)
{
    float y;
    asm("ex2.approx.f32 %0, %1;" : "=f"(y) : "f"(x));
    return y;
}

__device__ __forceinline__ void cpa16(uint32_t s, const void* g)
{
    asm volatile("cp.async.cg.shared.global [%0], [%1], 16;" :: "r"(s), "l"(g));
}
__device__ __forceinline__ void cpa8(uint32_t s, const void* g)
{
    asm volatile("cp.async.ca.shared.global [%0], [%1], 8;" :: "r"(s), "l"(g));
}
#define CP_COMMIT() asm volatile("cp.async.commit_group;")
#define CP_WAIT0()  asm volatile("cp.async.wait_group 0;")

// ---------------------------------------------------------------------------
// Conversion kernels
// ---------------------------------------------------------------------------
__global__ __launch_bounds__(256)
void convert_x_kernel(const float* __restrict__ x)
{
    const int i = (blockIdx.x * 256 + threadIdx.x) * 4;
    float4 v = *(const float4*)&x[i];
    __half h0 = __float2half_rn(v.x), h1 = __float2half_rn(v.y);
    __half h2 = __float2half_rn(v.z), h3 = __float2half_rn(v.w);
    __half l0 = __float2half_rn(v.x - __half2float(h0));
    __half l1 = __float2half_rn(v.y - __half2float(h1));
    __half l2 = __float2half_rn(v.z - __half2float(h2));
    __half l3 = __float2half_rn(v.w - __half2float(h3));
    *(__half2*)&g_xh[i]     = __halves2half2(h0, h1);
    *(__half2*)&g_xh[i + 2] = __halves2half2(h2, h3);
    *(__half2*)&g_xl[i]     = __halves2half2(l0, l1);
    *(__half2*)&g_xl[i + 2] = __halves2half2(l2, l3);
}

// w [K][Nw] fp32 -> wt_hi/lo [Nw][K] half
__global__ __launch_bounds__(256)
void convert_w_kernel(const float* __restrict__ w, __half* __restrict__ wth,
                      __half* __restrict__ wtl, int K, int Nw)
{
    const int idx = blockIdx.x * 256 + threadIdx.x;  // = n*K + k
    const int n = idx / K, k = idx % K;
    const float v = w[(size_t)k * Nw + n];
    const __half hi = __float2half_rn(v);
    wth[idx] = hi;
    wtl[idx] = __float2half_rn(v - __half2float(hi));
}

// ---------------------------------------------------------------------------
// HMMA GEMM (R6-proven, unchanged): C[M,Nw] = A[M,256] @ B[256,Nw] + bias.
// Block tile 128x64, BK=16, 8 warps (4x2), warp tile 32x32.
// 2-stage cp.async double buffer, STATIC SMEM, 1 sync per iter.
// MODE 0: scatter to Q/K/V arrays (QKV GEMM, Nw=768)
// MODE 1: plain fp32 out + bias (proj GEMM, Nw=256)
// ---------------------------------------------------------------------------
#define ASTR2 24   // 16 + 8 pad halfs -> conflict-free fragment LDS

template <int MODE>
__global__ __launch_bounds__(256)
void hgemm_kernel(const __half* __restrict__ Ah, const __half* __restrict__ Al,
                  const __half* __restrict__ Bth, const __half* __restrict__ Btl,
                  const float* __restrict__ bias, float* __restrict__ Cout,
                  int Nw)
{
    __shared__ __align__(16) __half sA[2][2][128][ASTR2];  // [stage][hi/lo][row][k]
    __shared__ __align__(16) __half sB[2][2][64][ASTR2];

    const int tid  = threadIdx.x;
    const int warp = tid >> 5;
    const int lane = tid & 31;
    const int g    = lane >> 2;
    const int t4   = lane & 3;
    const int m_base = (warp >> 1) * 32;
    const int n_base = (warp & 1) * 32;
    const int row0 = blockIdx.y * 128;
    const int col0 = blockIdx.x * 64;

    // global load mappings (per 16-wide K slice)
    const int ar = tid >> 1, ac = (tid & 1) * 8;   // A: 128 rows x 16 cols, 8 halfs/thread
    const int bn = tid >> 2, bc = (tid & 3) * 4;   // B: 64 rows x 16 cols, 4 halfs/thread
    const __half* pAh = Ah  + (size_t)(row0 + ar) * C_ + ac;
    const __half* pAl = Al  + (size_t)(row0 + ar) * C_ + ac;
    const __half* pBh = Bth + (size_t)(col0 + bn) * C_ + bc;
    const __half* pBl = Btl + (size_t)(col0 + bn) * C_ + bc;

    const uint32_t sAh_addr0 = (uint32_t)__cvta_generic_to_shared(&sA[0][0][ar][ac]);
    const uint32_t sAl_addr0 = (uint32_t)__cvta_generic_to_shared(&sA[0][1][ar][ac]);
    const uint32_t sBh_addr0 = (uint32_t)__cvta_generic_to_shared(&sB[0][0][bn][bc]);
    const uint32_t sBl_addr0 = (uint32_t)__cvta_generic_to_shared(&sB[0][1][bn][bc]);
    const uint32_t aStage = 2 * 128 * ASTR2 * 2;   // bytes per stage of sA
    const uint32_t bStage = 2 * 64 * ASTR2 * 2;

    float acc[2][4][4];
#pragma unroll
    for (int mf = 0; mf < 2; mf++)
#pragma unroll
        for (int nf = 0; nf < 4; nf++)
#pragma unroll
            for (int i = 0; i < 4; i++) acc[mf][nf][i] = 0.f;

    // prologue: issue tile 0
    {
        cpa16(sAh_addr0, pAh);
        cpa16(sAl_addr0, pAl);
        cpa8(sBh_addr0, pBh);
        cpa8(sBl_addr0, pBl);
        CP_COMMIT();
    }

    for (int it = 0; it < C_ / 16; it++) {
        CP_WAIT0();
        __syncthreads();
        if (it + 1 < C_ / 16) {
            const int s = (it + 1) & 1;
            const int k0 = (it + 1) * 16;
            cpa16(sAh_addr0 + s * aStage, pAh + k0);
            cpa16(sAl_addr0 + s * aStage, pAl + k0);
            cpa8(sBh_addr0 + s * bStage, pBh + k0);
            cpa8(sBl_addr0 + s * bStage, pBl + k0);
            CP_COMMIT();
        }
        const int s = it & 1;

        uint32_t ah[2][4], al[2][4];
#pragma unroll
        for (int mf = 0; mf < 2; mf++) {
            const int r = m_base + mf * 16;
            ah[mf][0] = *(const uint32_t*)&sA[s][0][r + g][2 * t4];
            ah[mf][1] = *(const uint32_t*)&sA[s][0][r + g + 8][2 * t4];
            ah[mf][2] = *(const uint32_t*)&sA[s][0][r + g][2 * t4 + 8];
            ah[mf][3] = *(const uint32_t*)&sA[s][0][r + g + 8][2 * t4 + 8];
            al[mf][0] = *(const uint32_t*)&sA[s][1][r + g][2 * t4];
            al[mf][1] = *(const uint32_t*)&sA[s][1][r + g + 8][2 * t4];
            al[mf][2] = *(const uint32_t*)&sA[s][1][r + g][2 * t4 + 8];
            al[mf][3] = *(const uint32_t*)&sA[s][1][r + g + 8][2 * t4 + 8];
        }
#pragma unroll
        for (int nf = 0; nf < 4; nf++) {
            const int n = n_base + nf * 8 + g;
            const uint32_t bh0 = *(const uint32_t*)&sB[s][0][n][2 * t4];
            const uint32_t bh1 = *(const uint32_t*)&sB[s][0][n][2 * t4 + 8];
            const uint32_t bl0 = *(const uint32_t*)&sB[s][1][n][2 * t4];
            const uint32_t bl1 = *(const uint32_t*)&sB[s][1][n][2 * t4 + 8];
#pragma unroll
            for (int mf = 0; mf < 2; mf++) {
                mma16816(acc[mf][nf], ah[mf], bh0, bh1);
                mma16816(acc[mf][nf], ah[mf], bl0, bl1);
                mma16816(acc[mf][nf], al[mf], bh0, bh1);
            }
        }
    }

    // --- epilogue ---
#pragma unroll
    for (int mf = 0; mf < 2; mf++) {
#pragma unroll
        for (int nf = 0; nf < 4; nf++) {
#pragma unroll
            for (int ii = 0; ii < 2; ii++) {
                const int mrow = row0 + m_base + mf * 16 + g + ii * 8;
                const int ncol = col0 + n_base + nf * 8 + 2 * t4;
                float v0 = acc[mf][nf][ii * 2]     + bias[ncol];
                float v1 = acc[mf][nf][ii * 2 + 1] + bias[ncol + 1];
                if (MODE == 0) {
                    const int b = mrow >> 11, nn = mrow & 2047;
                    const int s = ncol >> 8, rem = ncol & 255;
                    const int h = rem >> 4, d = rem & 15;
                    const int bh = (b << 4) + h;
                    if (s == 0) { v0 *= L2E; v1 *= L2E; }
                    const __half h0 = __float2half_rn(v0);
                    const __half h1 = __float2half_rn(v1);
                    if (s == 2) {
                        // V: fp16 only (error rides the same averaging as out)
                        g_vthi[((size_t)bh * D_ + d) * N_ + nn]     = h0;
                        g_vthi[((size_t)bh * D_ + d + 1) * N_ + nn] = h1;
                    } else {
                        const __half l0 = __float2half_rn(v0 - __half2float(h0));
                        const __half l1 = __float2half_rn(v1 - __half2float(h1));
                        const size_t idx = ((size_t)bh * N_ + nn) * D_ + d;
                        if (s == 0) {
                            *(__half2*)&g_qhi[idx] = __halves2half2(h0, h1);
                            *(__half2*)&g_qlo[idx] = __halves2half2(l0, l1);
                        } else {
                            *(__half2*)&g_khi[idx] = __halves2half2(h0, h1);
                            *(__half2*)&g_klo[idx] = __halves2half2(l0, l1);
                        }
                    }
                } else {
                    float2 o; o.x = v0; o.y = v1;
                    *(float2*)&Cout[(size_t)mrow * Nw + ncol] = o;
                }
            }
        }
    }
}

// ---------------------------------------------------------------------------
// FA2-style attention: 8 warps, 128 queries/CTA (16/warp), 64-key tiles.
// ILP-restructured: QK as 3 passes of 8 independent MMAs (chain depth 3->1);
// PV/L with dual accumulators (chain depth 4->2).
// ---------------------------------------------------------------------------
#define KSTRIDE 24
#define VSTRIDE 72

__global__ __launch_bounds__(256)
void attn_mma_kernel()
{
    __shared__ __align__(16) __half sKh[2][64][KSTRIDE];
    __shared__ __align__(16) __half sKl[2][64][KSTRIDE];
    __shared__ __align__(16) __half sVh[2][16][VSTRIDE];

    const int tid  = threadIdx.x;
    const int warp = tid >> 5;
    const int lane = tid & 31;
    const int g    = lane >> 2;
    const int t4   = lane & 3;
    const int bh   = blockIdx.y;
    const int q0   = blockIdx.x * 128 + warp * 16;

    // --- Q fragments ---
    uint32_t qh[4], ql[4];
    {
        const __half* qb_hi = &g_qhi[((size_t)bh * N_ + q0) * D_];
        const __half* qb_lo = &g_qlo[((size_t)bh * N_ + q0) * D_];
        qh[0] = *(const uint32_t*)&qb_hi[(g)     * D_ + 2 * t4];
        qh[1] = *(const uint32_t*)&qb_hi[(g + 8) * D_ + 2 * t4];
        qh[2] = *(const uint32_t*)&qb_hi[(g)     * D_ + 2 * t4 + 8];
        qh[3] = *(const uint32_t*)&qb_hi[(g + 8) * D_ + 2 * t4 + 8];
        ql[0] = *(const uint32_t*)&qb_lo[(g)     * D_ + 2 * t4];
        ql[1] = *(const uint32_t*)&qb_lo[(g + 8) * D_ + 2 * t4];
        ql[2] = *(const uint32_t*)&qb_lo[(g)     * D_ + 2 * t4 + 8];
        ql[3] = *(const uint32_t*)&qb_lo[(g + 8) * D_ + 2 * t4 + 8];
    }

    float O[2][4], O2[2][4];
#pragma unroll
    for (int dt = 0; dt < 2; dt++)
#pragma unroll
        for (int i = 0; i < 4; i++) { O[dt][i] = 0.f; O2[dt][i] = 0.f; }
    float L[4]  = {0.f, 0.f, 0.f, 0.f};   // ones-column accumulators
    float L2[4] = {0.f, 0.f, 0.f, 0.f};
    float m0 = -1e30f, m1 = -1e30f;

    const uint32_t bone = (g == 0) ? 0x3C003C00u : 0u;  // ones B-fragment (row n=0)

    // K/V tile load mapping
    const int kk  = tid >> 2;              // 0..63
    const int kdg = (tid & 3) * 4;
    const int vd  = tid >> 4;              // 0..15
    const int vkg = (tid & 15) * 4;
    const __half* gk_hi = &g_khi[((size_t)bh * N_ + kk) * D_ + kdg];
    const __half* gk_lo = &g_klo[((size_t)bh * N_ + kk) * D_ + kdg];
    const __half* gv_hi = &g_vthi[((size_t)bh * D_ + vd) * N_ + vkg];

    const uint32_t aKh = (uint32_t)__cvta_generic_to_shared(&sKh[0][kk][kdg]);
    const uint32_t aKl = (uint32_t)__cvta_generic_to_shared(&sKl[0][kk][kdg]);
    const uint32_t aVh = (uint32_t)__cvta_generic_to_shared(&sVh[0][vd][vkg]);
    const uint32_t kStage = 64 * KSTRIDE * 2;
    const uint32_t vStage = 16 * VSTRIDE * 2;

    // prologue: tile 0
    cpa8(aKh, gk_hi);
    cpa8(aKl, gk_lo);
    cpa8(aVh, gv_hi);
    CP_COMMIT();

    for (int kt = 0; kt < N_ / 64; kt++) {
        CP_WAIT0();
        __syncthreads();
        if (kt + 1 < N_ / 64) {
            const uint32_t s = (kt + 1) & 1;
            cpa8(aKh + s * kStage, gk_hi + (size_t)(kt + 1) * 64 * D_);
            cpa8(aKl + s * kStage, gk_lo + (size_t)(kt + 1) * 64 * D_);
            cpa8(aVh + s * vStage, gv_hi + (kt + 1) * 64);
            CP_COMMIT();
        }
        const int s = kt & 1;

        // --- preload all K fragments (hi + lo) for this tile ---
        uint32_t kh0[8], kh1[8], kl0[8], kl1[8];
#pragma unroll
        for (int nt = 0; nt < 8; nt++) {
            const int key = nt * 8 + g;
            kh0[nt] = *(const uint32_t*)&sKh[s][key][2 * t4];
            kh1[nt] = *(const uint32_t*)&sKh[s][key][2 * t4 + 8];
            kl0[nt] = *(const uint32_t*)&sKl[s][key][2 * t4];
            kl1[nt] = *(const uint32_t*)&sKl[s][key][2 * t4 + 8];
        }

        // --- S = Q Kᵀ : 3 passes of 8 independent MMAs each ---
        float S[8][4];
#pragma unroll
        for (int nt = 0; nt < 8; nt++) {
#pragma unroll
            for (int i = 0; i < 4; i++) S[nt][i] = 0.f;
        }
#pragma unroll
        for (int nt = 0; nt < 8; nt++) mma16816(S[nt], qh, kh0[nt], kh1[nt]);
#pragma unroll
        for (int nt = 0; nt < 8; nt++) mma16816(S[nt], qh, kl0[nt], kl1[nt]);
#pragma unroll
        for (int nt = 0; nt < 8; nt++) mma16816(S[nt], ql, kh0[nt], kh1[nt]);

        // --- online max (log2 domain) ---
        float cm0 = m0, cm1 = m1;
#pragma unroll
        for (int nt = 0; nt < 8; nt++) {
            cm0 = fmaxf(cm0, fmaxf(S[nt][0], S[nt][1]));
            cm1 = fmaxf(cm1, fmaxf(S[nt][2], S[nt][3]));
        }
        cm0 = fmaxf(cm0, __shfl_xor_sync(0xffffffffu, cm0, 1));
        cm0 = fmaxf(cm0, __shfl_xor_sync(0xffffffffu, cm0, 2));
        cm1 = fmaxf(cm1, __shfl_xor_sync(0xffffffffu, cm1, 1));
        cm1 = fmaxf(cm1, __shfl_xor_sync(0xffffffffu, cm1, 2));

        const float corr0 = ex2(m0 - cm0);
        const float corr1 = ex2(m1 - cm1);
        m0 = cm0; m1 = cm1;
#pragma unroll
        for (int dt = 0; dt < 2; dt++) {
            O[dt][0]  *= corr0; O[dt][1]  *= corr0;
            O[dt][2]  *= corr1; O[dt][3]  *= corr1;
            O2[dt][0] *= corr0; O2[dt][1] *= corr0;
            O2[dt][2] *= corr1; O2[dt][3] *= corr1;
        }
        L[0] *= corr0; L[2] *= corr1;
        L2[0] *= corr0; L2[2] *= corr1;

        // --- P = exp2(S - m) directly in packed fp16 ---
        uint32_t P[4][4];
#pragma unroll
        for (int kt2 = 0; kt2 < 4; kt2++) {
            P[kt2][0] = ex2_f16x2(packf16(S[2 * kt2][0] - cm0,     S[2 * kt2][1] - cm0));
            P[kt2][1] = ex2_f16x2(packf16(S[2 * kt2][2] - cm1,     S[2 * kt2][3] - cm1));
            P[kt2][2] = ex2_f16x2(packf16(S[2 * kt2 + 1][0] - cm0, S[2 * kt2 + 1][1] - cm0));
            P[kt2][3] = ex2_f16x2(packf16(S[2 * kt2 + 1][2] - cm1, S[2 * kt2 + 1][3] - cm1));
        }

        // --- O += P V (fp16 V), l += P @ ones ; dual accumulators ---
#pragma unroll
        for (int kt2 = 0; kt2 < 4; kt2++) {
            float* Lacc = (kt2 & 1) ? L2 : L;
            mma16816(Lacc, P[kt2], bone, bone);
#pragma unroll
            for (int dt = 0; dt < 2; dt++) {
                const int drow = dt * 8 + g;
                uint32_t vh0 = *(const uint32_t*)&sVh[s][drow][kt2 * 16 + 2 * t4];
                uint32_t vh1 = *(const uint32_t*)&sVh[s][drow][kt2 * 16 + 2 * t4 + 8];
                float* Oacc = (kt2 & 1) ? O2[dt] : O[dt];
                mma16816(Oacc, P[kt2], vh0, vh1);
            }
        }
    }

    // --- epilogue: merge dual accumulators, fetch l, normalize, write ---
    const float lsum0 = L[0] + L2[0];
    const float lsum1 = L[2] + L2[2];
    const float lf0 = __shfl_sync(0xffffffffu, lsum0, lane & 28);
    const float lf1 = __shfl_sync(0xffffffffu, lsum1, lane & 28);
    const float inv0 = 1.f / lf0;
    const float inv1 = 1.f / lf1;

    const int b = bh >> 4, h = bh & 15;
    const size_t r0 = ((size_t)(b * N_ + q0 + g))     * C_ + h * D_;
    const size_t r1 = ((size_t)(b * N_ + q0 + g + 8)) * C_ + h * D_;
#pragma unroll
    for (int dt = 0; dt < 2; dt++) {
        const float a0 = (O[dt][0] + O2[dt][0]) * inv0;
        const float a1 = (O[dt][1] + O2[dt][1]) * inv0;
        const float b0 = (O[dt][2] + O2[dt][2]) * inv1;
        const float b1 = (O[dt][3] + O2[dt][3]) * inv1;
        const __half ah0 = __float2half_rn(a0), ah1 = __float2half_rn(a1);
        const __half bh0 = __float2half_rn(b0), bh1 = __float2half_rn(b1);
        const __half al0 = __float2half_rn(a0 - __half2float(ah0));
        const __half al1 = __float2half_rn(a1 - __half2float(ah1));
        const __half bl0 = __float2half_rn(b0 - __half2float(bh0));
        const __half bl1 = __float2half_rn(b1 - __half2float(bh1));
        const size_t c = dt * 8 + 2 * t4;
        *(__half2*)&g_atth[r0 + c] = __halves2half2(ah0, ah1);
        *(__half2*)&g_attl[r0 + c] = __halves2half2(al0, al1);
        *(__half2*)&g_atth[r1 + c] = __halves2half2(bh0, bh1);
        *(__half2*)&g_attl[r1 + c] = __halves2half2(bl0, bl1);
    }
}

// ---------------------------------------------------------------------------
extern "C" void kernel_launch(void* const* d_in, const int* in_sizes, int n_in,
                              void* d_out, int out_size)
{
    const float* x      = (const float*)d_in[0];   // (B,N,C)
    const float* w_qkv  = (const float*)d_in[1];   // (C,3C)
    const float* b_qkv  = (const float*)d_in[2];   // (3C,)
    const float* w_proj = (const float*)d_in[3];   // (C,C)
    const float* b_proj = (const float*)d_in[4];   // (C,)
    float* out = (float*)d_out;

    __half *xh, *xl, *wqt_h, *wqt_l, *wpt_h, *wpt_l, *atth, *attl;
    cudaGetSymbolAddress((void**)&xh, g_xh);
    cudaGetSymbolAddress((void**)&xl, g_xl);
    cudaGetSymbolAddress((void**)&wqt_h, g_wqt_h);
    cudaGetSymbolAddress((void**)&wqt_l, g_wqt_l);
    cudaGetSymbolAddress((void**)&wpt_h, g_wpt_h);
    cudaGetSymbolAddress((void**)&wpt_l, g_wpt_l);
    cudaGetSymbolAddress((void**)&atth, g_atth);
    cudaGetSymbolAddress((void**)&attl, g_attl);

    // 0) conversions
    convert_x_kernel<<<M_ * C_ / 4 / 256, 256>>>(x);
    convert_w_kernel<<<C_ * K3_ / 256, 256>>>(w_qkv, wqt_h, wqt_l, C_, K3_);
    convert_w_kernel<<<C_ * C_ / 256, 256>>>(w_proj, wpt_h, wpt_l, C_, C_);

    // 1) QKV GEMM (HMMA) + scatter: (8192x256)@(256x768)
    {
        dim3 grid(K3_ / 64, M_ / 128);
        hgemm_kernel<0><<<grid, 256>>>(xh, xl, wqt_h, wqt_l, b_qkv, nullptr, K3_);
    }
    // 2) Attention (tensor cores)
    {
        dim3 grid(N_ / 128, BH_);
        attn_mma_kernel<<<grid, 256>>>();
    }
    // 3) Output projection (HMMA): (8192x256)@(256x256)
    {
        dim3 grid(C_ / 64, M_ / 128);
        hgemm_kernel<1><<<grid, 256>>>(atth, attl, wpt_h, wpt_l, b_proj, out, C_);
    }
}

// round 11
// speedup vs baseline: 1.0302x; 1.0302x over previous
#include <cuda_runtime.h>
#include <cuda_fp16.h>
#include <stdint.h>

// Problem constants
#define B_   4
#define N_   2048
#define C_   256
#define H_   16
#define D_   16
#define BH_  (B_ * H_)          // 64
#define M_   (B_ * N_)          // 8192
#define K3_  (3 * C_)           // 768

#define L2E 1.4426950408889634f

// ---------------------------------------------------------------------------
// Scratch (device globals — no allocations allowed)
// ---------------------------------------------------------------------------
__device__ __align__(128) __half g_xh[M_ * C_],  g_xl[M_ * C_];      // x hi/lo [M][C]
__device__ __align__(128) __half g_wqt_h[K3_ * C_], g_wqt_l[K3_ * C_]; // w_qkv^T [768][256]
__device__ __align__(128) __half g_wpt_h[C_ * C_],  g_wpt_l[C_ * C_];  // w_proj^T [256][256]

__device__ __align__(128) __half g_qhi[BH_ * N_ * D_], g_qlo[BH_ * N_ * D_]; // [bh][n][d]
__device__ __align__(128) __half g_khi[BH_ * N_ * D_], g_klo[BH_ * N_ * D_];
__device__ __align__(128) __half g_vthi[BH_ * D_ * N_];               // [bh][d][n] (fp16 only)

__device__ __align__(128) __half g_atth[M_ * C_], g_attl[M_ * C_];   // attn out hi/lo [M][C]

// ---------------------------------------------------------------------------
// helpers
// ---------------------------------------------------------------------------
__device__ __forceinline__ void mma16816(float* c, const uint32_t* a,
                                         uint32_t b0, uint32_t b1)
{
    asm volatile(
        "mma.sync.aligned.m16n8k16.row.col.f32.f16.f16.f32 "
        "{%0,%1,%2,%3}, {%4,%5,%6,%7}, {%8,%9}, {%0,%1,%2,%3};"
        : "+f"(c[0]), "+f"(c[1]), "+f"(c[2]), "+f"(c[3])
        : "r"(a[0]), "r"(a[1]), "r"(a[2]), "r"(a[3]), "r"(b0), "r"(b1));
}

__device__ __forceinline__ uint32_t packf16(float lo, float hi)
{
    uint32_t r;
    asm("cvt.rn.f16x2.f32 %0, %1, %2;" : "=r"(r) : "f"(hi), "f"(lo));
    return r;
}

__device__ __forceinline__ uint32_t ex2_f16x2(uint32_t a)
{
    uint32_t r;
    asm("ex2.approx.f16x2 %0, %1;" : "=r"(r) : "r"(a));
    return r;
}

__device__ __forceinline__ float ex2(float x)
{
    float y;
    asm("ex2.approx.f32 %0, %1;" : "=f"(y) : "f"(x));
    return y;
}

__device__ __forceinline__ float sum2_f16(uint32_t p)
{
    const float2 f = __half22float2(*(const __half2*)&p);
    return f.x + f.y;
}

__device__ __forceinline__ void cpa16(uint32_t s, const void* g)
{
    asm volatile("cp.async.cg.shared.global [%0], [%1], 16;" :: "r"(s), "l"(g));
}
__device__ __forceinline__ void cpa8(uint32_t s, const void* g)
{
    asm volatile("cp.async.ca.shared.global [%0], [%1], 8;" :: "r"(s), "l"(g));
}
#define CP_COMMIT() asm volatile("cp.async.commit_group;")
#define CP_WAIT0()  asm volatile("cp.async.wait_group 0;")

// ---------------------------------------------------------------------------
// Conversion kernels
// ---------------------------------------------------------------------------
__global__ __launch_bounds__(256)
void convert_x_kernel(const float* __restrict__ x)
{
    const int i = (blockIdx.x * 256 + threadIdx.x) * 4;
    float4 v = *(const float4*)&x[i];
    __half h0 = __float2half_rn(v.x), h1 = __float2half_rn(v.y);
    __half h2 = __float2half_rn(v.z), h3 = __float2half_rn(v.w);
    __half l0 = __float2half_rn(v.x - __half2float(h0));
    __half l1 = __float2half_rn(v.y - __half2float(h1));
    __half l2 = __float2half_rn(v.z - __half2float(h2));
    __half l3 = __float2half_rn(v.w - __half2float(h3));
    *(__half2*)&g_xh[i]     = __halves2half2(h0, h1);
    *(__half2*)&g_xh[i + 2] = __halves2half2(h2, h3);
    *(__half2*)&g_xl[i]     = __halves2half2(l0, l1);
    *(__half2*)&g_xl[i + 2] = __halves2half2(l2, l3);
}

// w [K][Nw] fp32 -> wt_hi/lo [Nw][K] half
__global__ __launch_bounds__(256)
void convert_w_kernel(const float* __restrict__ w, __half* __restrict__ wth,
                      __half* __restrict__ wtl, int K, int Nw)
{
    const int idx = blockIdx.x * 256 + threadIdx.x;  // = n*K + k
    const int n = idx / K, k = idx % K;
    const float v = w[(size_t)k * Nw + n];
    const __half hi = __float2half_rn(v);
    wth[idx] = hi;
    wtl[idx] = __float2half_rn(v - __half2float(hi));
}

// ---------------------------------------------------------------------------
// HMMA GEMM: C[M,Nw] = A[M,256] @ B[256,Nw] + bias.
// Block tile 128x64, BK=16, 8 warps (4x2), warp tile 32x32.
// 2-stage cp.async double buffer, STATIC SMEM, 1 sync per iter.
// MODE 0: scatter to Q/K/V arrays (QKV GEMM, Nw=768).
//         V column-tiles (col0>=512) use single fp16 MMA (no hi/lo correction).
// MODE 1: plain fp32 out + bias (proj GEMM, Nw=256)
// ---------------------------------------------------------------------------
#define ASTR2 24   // 16 + 8 pad halfs -> conflict-free fragment LDS

template <int MODE>
__global__ __launch_bounds__(256)
void hgemm_kernel(const __half* __restrict__ Ah, const __half* __restrict__ Al,
                  const __half* __restrict__ Bth, const __half* __restrict__ Btl,
                  const float* __restrict__ bias, float* __restrict__ Cout,
                  int Nw)
{
    __shared__ __align__(16) __half sA[2][2][128][ASTR2];  // [stage][hi/lo][row][k]
    __shared__ __align__(16) __half sB[2][2][64][ASTR2];

    const int tid  = threadIdx.x;
    const int warp = tid >> 5;
    const int lane = tid & 31;
    const int g    = lane >> 2;
    const int t4   = lane & 3;
    const int m_base = (warp >> 1) * 32;
    const int n_base = (warp & 1) * 32;
    const int row0 = blockIdx.y * 128;
    const int col0 = blockIdx.x * 64;

    // V tile: fp16-precision output is enough -> single hi*hi MMA, no lo streams
    const bool vtile = (MODE == 0) && (col0 >= 512);

    // global load mappings (per 16-wide K slice)
    const int ar = tid >> 1, ac = (tid & 1) * 8;   // A: 128 rows x 16 cols, 8 halfs/thread
    const int bn = tid >> 2, bc = (tid & 3) * 4;   // B: 64 rows x 16 cols, 4 halfs/thread
    const __half* pAh = Ah  + (size_t)(row0 + ar) * C_ + ac;
    const __half* pAl = Al  + (size_t)(row0 + ar) * C_ + ac;
    const __half* pBh = Bth + (size_t)(col0 + bn) * C_ + bc;
    const __half* pBl = Btl + (size_t)(col0 + bn) * C_ + bc;

    const uint32_t sAh_addr0 = (uint32_t)__cvta_generic_to_shared(&sA[0][0][ar][ac]);
    const uint32_t sAl_addr0 = (uint32_t)__cvta_generic_to_shared(&sA[0][1][ar][ac]);
    const uint32_t sBh_addr0 = (uint32_t)__cvta_generic_to_shared(&sB[0][0][bn][bc]);
    const uint32_t sBl_addr0 = (uint32_t)__cvta_generic_to_shared(&sB[0][1][bn][bc]);
    const uint32_t aStage = 2 * 128 * ASTR2 * 2;   // bytes per stage of sA
    const uint32_t bStage = 2 * 64 * ASTR2 * 2;

    float acc[2][4][4];
#pragma unroll
    for (int mf = 0; mf < 2; mf++)
#pragma unroll
        for (int nf = 0; nf < 4; nf++)
#pragma unroll
            for (int i = 0; i < 4; i++) acc[mf][nf][i] = 0.f;

    // prologue: issue tile 0
    {
        cpa16(sAh_addr0, pAh);
        cpa8(sBh_addr0, pBh);
        if (!vtile) {
            cpa16(sAl_addr0, pAl);
            cpa8(sBl_addr0, pBl);
        }
        CP_COMMIT();
    }

    for (int it = 0; it < C_ / 16; it++) {
        CP_WAIT0();
        __syncthreads();
        if (it + 1 < C_ / 16) {
            const int s = (it + 1) & 1;
            const int k0 = (it + 1) * 16;
            cpa16(sAh_addr0 + s * aStage, pAh + k0);
            cpa8(sBh_addr0 + s * bStage, pBh + k0);
            if (!vtile) {
                cpa16(sAl_addr0 + s * aStage, pAl + k0);
                cpa8(sBl_addr0 + s * bStage, pBl + k0);
            }
            CP_COMMIT();
        }
        const int s = it & 1;

        uint32_t ah[2][4], al[2][4];
#pragma unroll
        for (int mf = 0; mf < 2; mf++) {
            const int r = m_base + mf * 16;
            ah[mf][0] = *(const uint32_t*)&sA[s][0][r + g][2 * t4];
            ah[mf][1] = *(const uint32_t*)&sA[s][0][r + g + 8][2 * t4];
            ah[mf][2] = *(const uint32_t*)&sA[s][0][r + g][2 * t4 + 8];
            ah[mf][3] = *(const uint32_t*)&sA[s][0][r + g + 8][2 * t4 + 8];
            if (!vtile) {
                al[mf][0] = *(const uint32_t*)&sA[s][1][r + g][2 * t4];
                al[mf][1] = *(const uint32_t*)&sA[s][1][r + g + 8][2 * t4];
                al[mf][2] = *(const uint32_t*)&sA[s][1][r + g][2 * t4 + 8];
                al[mf][3] = *(const uint32_t*)&sA[s][1][r + g + 8][2 * t4 + 8];
            }
        }
#pragma unroll
        for (int nf = 0; nf < 4; nf++) {
            const int n = n_base + nf * 8 + g;
            const uint32_t bh0 = *(const uint32_t*)&sB[s][0][n][2 * t4];
            const uint32_t bh1 = *(const uint32_t*)&sB[s][0][n][2 * t4 + 8];
#pragma unroll
            for (int mf = 0; mf < 2; mf++)
                mma16816(acc[mf][nf], ah[mf], bh0, bh1);
            if (!vtile) {
                const uint32_t bl0 = *(const uint32_t*)&sB[s][1][n][2 * t4];
                const uint32_t bl1 = *(const uint32_t*)&sB[s][1][n][2 * t4 + 8];
#pragma unroll
                for (int mf = 0; mf < 2; mf++) {
                    mma16816(acc[mf][nf], ah[mf], bl0, bl1);
                    mma16816(acc[mf][nf], al[mf], bh0, bh1);
                }
            }
        }
    }

    // --- epilogue ---
#pragma unroll
    for (int mf = 0; mf < 2; mf++) {
#pragma unroll
        for (int nf = 0; nf < 4; nf++) {
#pragma unroll
            for (int ii = 0; ii < 2; ii++) {
                const int mrow = row0 + m_base + mf * 16 + g + ii * 8;
                const int ncol = col0 + n_base + nf * 8 + 2 * t4;
                float v0 = acc[mf][nf][ii * 2]     + bias[ncol];
                float v1 = acc[mf][nf][ii * 2 + 1] + bias[ncol + 1];
                if (MODE == 0) {
                    const int b = mrow >> 11, nn = mrow & 2047;
                    const int s = ncol >> 8, rem = ncol & 255;
                    const int h = rem >> 4, d = rem & 15;
                    const int bh = (b << 4) + h;
                    if (s == 0) { v0 *= L2E; v1 *= L2E; }
                    const __half h0 = __float2half_rn(v0);
                    const __half h1 = __float2half_rn(v1);
                    if (s == 2) {
                        g_vthi[((size_t)bh * D_ + d) * N_ + nn]     = h0;
                        g_vthi[((size_t)bh * D_ + d + 1) * N_ + nn] = h1;
                    } else {
                        const __half l0 = __float2half_rn(v0 - __half2float(h0));
                        const __half l1 = __float2half_rn(v1 - __half2float(h1));
                        const size_t idx = ((size_t)bh * N_ + nn) * D_ + d;
                        if (s == 0) {
                            *(__half2*)&g_qhi[idx] = __halves2half2(h0, h1);
                            *(__half2*)&g_qlo[idx] = __halves2half2(l0, l1);
                        } else {
                            *(__half2*)&g_khi[idx] = __halves2half2(h0, h1);
                            *(__half2*)&g_klo[idx] = __halves2half2(l0, l1);
                        }
                    }
                } else {
                    float2 o; o.x = v0; o.y = v1;
                    *(float2*)&Cout[(size_t)mrow * Nw + ncol] = o;
                }
            }
        }
    }
}

// ---------------------------------------------------------------------------
// FA2-style attention: 8 warps, 128 queries/CTA (16/warp), 64-key tiles.
// QK hi/lo (3 passes of 8 MMAs), PV single fp16 V (8 MMAs).
// l computed on the ALU pipe from packed P (exact same values as an MMA would sum).
// 32 tensor MMAs per warp-ktile.
// ---------------------------------------------------------------------------
#define KSTRIDE 24
#define VSTRIDE 72

__global__ __launch_bounds__(256)
void attn_mma_kernel()
{
    __shared__ __align__(16) __half sKh[2][64][KSTRIDE];
    __shared__ __align__(16) __half sKl[2][64][KSTRIDE];
    __shared__ __align__(16) __half sVh[2][16][VSTRIDE];

    const int tid  = threadIdx.x;
    const int warp = tid >> 5;
    const int lane = tid & 31;
    const int g    = lane >> 2;
    const int t4   = lane & 3;
    const int bh   = blockIdx.y;
    const int q0   = blockIdx.x * 128 + warp * 16;

    // --- Q fragments ---
    uint32_t qh[4], ql[4];
    {
        const __half* qb_hi = &g_qhi[((size_t)bh * N_ + q0) * D_];
        const __half* qb_lo = &g_qlo[((size_t)bh * N_ + q0) * D_];
        qh[0] = *(const uint32_t*)&qb_hi[(g)     * D_ + 2 * t4];
        qh[1] = *(const uint32_t*)&qb_hi[(g + 8) * D_ + 2 * t4];
        qh[2] = *(const uint32_t*)&qb_hi[(g)     * D_ + 2 * t4 + 8];
        qh[3] = *(const uint32_t*)&qb_hi[(g + 8) * D_ + 2 * t4 + 8];
        ql[0] = *(const uint32_t*)&qb_lo[(g)     * D_ + 2 * t4];
        ql[1] = *(const uint32_t*)&qb_lo[(g + 8) * D_ + 2 * t4];
        ql[2] = *(const uint32_t*)&qb_lo[(g)     * D_ + 2 * t4 + 8];
        ql[3] = *(const uint32_t*)&qb_lo[(g + 8) * D_ + 2 * t4 + 8];
    }

    float O[2][4];
#pragma unroll
    for (int dt = 0; dt < 2; dt++)
#pragma unroll
        for (int i = 0; i < 4; i++) O[dt][i] = 0.f;
    float l0 = 0.f, l1 = 0.f;            // per-thread partial row sums (over its 16 key slots)
    float m0 = -1e30f, m1 = -1e30f;

    // K/V tile load mapping
    const int kk  = tid >> 2;              // 0..63
    const int kdg = (tid & 3) * 4;
    const int vd  = tid >> 4;              // 0..15
    const int vkg = (tid & 15) * 4;
    const __half* gk_hi = &g_khi[((size_t)bh * N_ + kk) * D_ + kdg];
    const __half* gk_lo = &g_klo[((size_t)bh * N_ + kk) * D_ + kdg];
    const __half* gv_hi = &g_vthi[((size_t)bh * D_ + vd) * N_ + vkg];

    const uint32_t aKh = (uint32_t)__cvta_generic_to_shared(&sKh[0][kk][kdg]);
    const uint32_t aKl = (uint32_t)__cvta_generic_to_shared(&sKl[0][kk][kdg]);
    const uint32_t aVh = (uint32_t)__cvta_generic_to_shared(&sVh[0][vd][vkg]);
    const uint32_t kStage = 64 * KSTRIDE * 2;
    const uint32_t vStage = 16 * VSTRIDE * 2;

    // prologue: tile 0
    cpa8(aKh, gk_hi);
    cpa8(aKl, gk_lo);
    cpa8(aVh, gv_hi);
    CP_COMMIT();

    for (int kt = 0; kt < N_ / 64; kt++) {
        CP_WAIT0();
        __syncthreads();
        if (kt + 1 < N_ / 64) {
            const uint32_t s = (kt + 1) & 1;
            cpa8(aKh + s * kStage, gk_hi + (size_t)(kt + 1) * 64 * D_);
            cpa8(aKl + s * kStage, gk_lo + (size_t)(kt + 1) * 64 * D_);
            cpa8(aVh + s * vStage, gv_hi + (kt + 1) * 64);
            CP_COMMIT();
        }
        const int s = kt & 1;

        // --- preload all K fragments (hi + lo) for this tile ---
        uint32_t kh0[8], kh1[8], kl0[8], kl1[8];
#pragma unroll
        for (int nt = 0; nt < 8; nt++) {
            const int key = nt * 8 + g;
            kh0[nt] = *(const uint32_t*)&sKh[s][key][2 * t4];
            kh1[nt] = *(const uint32_t*)&sKh[s][key][2 * t4 + 8];
            kl0[nt] = *(const uint32_t*)&sKl[s][key][2 * t4];
            kl1[nt] = *(const uint32_t*)&sKl[s][key][2 * t4 + 8];
        }

        // --- S = Q Kᵀ : 3 passes of 8 independent MMAs each ---
        float S[8][4];
#pragma unroll
        for (int nt = 0; nt < 8; nt++) {
#pragma unroll
            for (int i = 0; i < 4; i++) S[nt][i] = 0.f;
        }
#pragma unroll
        for (int nt = 0; nt < 8; nt++) mma16816(S[nt], qh, kh0[nt], kh1[nt]);
#pragma unroll
        for (int nt = 0; nt < 8; nt++) mma16816(S[nt], qh, kl0[nt], kl1[nt]);
#pragma unroll
        for (int nt = 0; nt < 8; nt++) mma16816(S[nt], ql, kh0[nt], kh1[nt]);

        // --- online max (log2 domain) ---
        float cm0 = m0, cm1 = m1;
#pragma unroll
        for (int nt = 0; nt < 8; nt++) {
            cm0 = fmaxf(cm0, fmaxf(S[nt][0], S[nt][1]));
            cm1 = fmaxf(cm1, fmaxf(S[nt][2], S[nt][3]));
        }
        cm0 = fmaxf(cm0, __shfl_xor_sync(0xffffffffu, cm0, 1));
        cm0 = fmaxf(cm0, __shfl_xor_sync(0xffffffffu, cm0, 2));
        cm1 = fmaxf(cm1, __shfl_xor_sync(0xffffffffu, cm1, 1));
        cm1 = fmaxf(cm1, __shfl_xor_sync(0xffffffffu, cm1, 2));

        const float corr0 = ex2(m0 - cm0);
        const float corr1 = ex2(m1 - cm1);
        m0 = cm0; m1 = cm1;
#pragma unroll
        for (int dt = 0; dt < 2; dt++) {
            O[dt][0] *= corr0; O[dt][1] *= corr0;
            O[dt][2] *= corr1; O[dt][3] *= corr1;
        }
        l0 *= corr0; l1 *= corr1;

        // --- P = exp2(S - m) directly in packed fp16 ---
        uint32_t P[4][4];
#pragma unroll
        for (int kt2 = 0; kt2 < 4; kt2++) {
            P[kt2][0] = ex2_f16x2(packf16(S[2 * kt2][0] - cm0,     S[2 * kt2][1] - cm0));
            P[kt2][1] = ex2_f16x2(packf16(S[2 * kt2][2] - cm1,     S[2 * kt2][3] - cm1));
            P[kt2][2] = ex2_f16x2(packf16(S[2 * kt2 + 1][0] - cm0, S[2 * kt2 + 1][1] - cm0));
            P[kt2][3] = ex2_f16x2(packf16(S[2 * kt2 + 1][2] - cm1, S[2 * kt2 + 1][3] - cm1));
        }

        // --- l partial sums on the ALU pipe (exact fp16->f32 accumulation) ---
#pragma unroll
        for (int kt2 = 0; kt2 < 4; kt2++) {
            l0 += sum2_f16(P[kt2][0]) + sum2_f16(P[kt2][2]);
            l1 += sum2_f16(P[kt2][1]) + sum2_f16(P[kt2][3]);
        }

        // --- O += P V (fp16 V) ---
#pragma unroll
        for (int kt2 = 0; kt2 < 4; kt2++) {
#pragma unroll
            for (int dt = 0; dt < 2; dt++) {
                const int drow = dt * 8 + g;
                uint32_t vh0 = *(const uint32_t*)&sVh[s][drow][kt2 * 16 + 2 * t4];
                uint32_t vh1 = *(const uint32_t*)&sVh[s][drow][kt2 * 16 + 2 * t4 + 8];
                mma16816(O[dt], P[kt2], vh0, vh1);
            }
        }
    }

    // --- epilogue: reduce l over the t4 quad, normalize, hi/lo write ---
    float lf0 = l0, lf1 = l1;
    lf0 += __shfl_xor_sync(0xffffffffu, lf0, 1);
    lf0 += __shfl_xor_sync(0xffffffffu, lf0, 2);
    lf1 += __shfl_xor_sync(0xffffffffu, lf1, 1);
    lf1 += __shfl_xor_sync(0xffffffffu, lf1, 2);
    const float inv0 = 1.f / lf0;
    const float inv1 = 1.f / lf1;

    const int b = bh >> 4, h = bh & 15;
    const size_t r0 = ((size_t)(b * N_ + q0 + g))     * C_ + h * D_;
    const size_t r1 = ((size_t)(b * N_ + q0 + g + 8)) * C_ + h * D_;
#pragma unroll
    for (int dt = 0; dt < 2; dt++) {
        const float a0 = O[dt][0] * inv0, a1 = O[dt][1] * inv0;
        const float b0 = O[dt][2] * inv1, b1 = O[dt][3] * inv1;
        const __half ah0 = __float2half_rn(a0), ah1 = __float2half_rn(a1);
        const __half bh0 = __float2half_rn(b0), bh1 = __float2half_rn(b1);
        const __half al0 = __float2half_rn(a0 - __half2float(ah0));
        const __half al1 = __float2half_rn(a1 - __half2float(ah1));
        const __half bl0 = __float2half_rn(b0 - __half2float(bh0));
        const __half bl1 = __float2half_rn(b1 - __half2float(bh1));
        const size_t c = dt * 8 + 2 * t4;
        *(__half2*)&g_atth[r0 + c] = __halves2half2(ah0, ah1);
        *(__half2*)&g_attl[r0 + c] = __halves2half2(al0, al1);
        *(__half2*)&g_atth[r1 + c] = __halves2half2(bh0, bh1);
        *(__half2*)&g_attl[r1 + c] = __halves2half2(bl0, bl1);
    }
}

// ---------------------------------------------------------------------------
extern "C" void kernel_launch(void* const* d_in, const int* in_sizes, int n_in,
                              void* d_out, int out_size)
{
    const float* x      = (const float*)d_in[0];   // (B,N,C)
    const float* w_qkv  = (const float*)d_in[1];   // (C,3C)
    const float* b_qkv  = (const float*)d_in[2];   // (3C,)
    const float* w_proj = (const float*)d_in[3];   // (C,C)
    const float* b_proj = (const float*)d_in[4];   // (C,)
    float* out = (float*)d_out;

    __half *xh, *xl, *wqt_h, *wqt_l, *wpt_h, *wpt_l, *atth, *attl;
    cudaGetSymbolAddress((void**)&xh, g_xh);
    cudaGetSymbolAddress((void**)&xl, g_xl);
    cudaGetSymbolAddress((void**)&wqt_h, g_wqt_h);
    cudaGetSymbolAddress((void**)&wqt_l, g_wqt_l);
    cudaGetSymbolAddress((void**)&wpt_h, g_wpt_h);
    cudaGetSymbolAddress((void**)&wpt_l, g_wpt_l);
    cudaGetSymbolAddress((void**)&atth, g_atth);
    cudaGetSymbolAddress((void**)&attl, g_attl);

    // 0) conversions
    convert_x_kernel<<<M_ * C_ / 4 / 256, 256>>>(x);
    convert_w_kernel<<<C_ * K3_ / 256, 256>>>(w_qkv, wqt_h, wqt_l, C_, K3_);
    convert_w_kernel<<<C_ * C_ / 256, 256>>>(w_proj, wpt_h, wpt_l, C_, C_);

    // 1) QKV GEMM (HMMA) + scatter: (8192x256)@(256x768)
    {
        dim3 grid(K3_ / 64, M_ / 128);
        hgemm_kernel<0><<<grid, 256>>>(xh, xl, wqt_h, wqt_l, b_qkv, nullptr, K3_);
    }
    // 2) Attention (tensor cores)
    {
        dim3 grid(N_ / 128, BH_);
        attn_mma_kernel<<<grid, 256>>>();
    }
    // 3) Output projection (HMMA): (8192x256)@(256x256)
    {
        dim3 grid(C_ / 64, M_ / 128);
        hgemm_kernel<1><<<grid, 256>>>(atth, attl, wpt_h, wpt_l, b_proj, out, C_);
    }
}

// round 13
// speedup vs baseline: 1.0625x; 1.0313x over previous
#include <cuda_runtime.h>
#include <cuda_fp16.h>
#include <stdint.h>

// Problem constants
#define B_   4
#define N_   2048
#define C_   256
#define H_   16
#define D_   16
#define BH_  (B_ * H_)          // 64
#define M_   (B_ * N_)          // 8192
#define K3_  (3 * C_)           // 768

#define L2E 1.4426950408889634f

// ---------------------------------------------------------------------------
// Scratch (device globals — no allocations allowed)
// ---------------------------------------------------------------------------
__device__ __align__(128) __half g_xh[M_ * C_],  g_xl[M_ * C_];      // x hi/lo [M][C]
__device__ __align__(128) __half g_wqt_h[K3_ * C_], g_wqt_l[K3_ * C_]; // w_qkv^T [768][256]
__device__ __align__(128) __half g_wpt_h[C_ * C_],  g_wpt_l[C_ * C_];  // w_proj^T [256][256]

__device__ __align__(128) __half g_qhi[BH_ * N_ * D_], g_qlo[BH_ * N_ * D_]; // [bh][n][d]
__device__ __align__(128) __half g_khi[BH_ * N_ * D_], g_klo[BH_ * N_ * D_];
__device__ __align__(128) __half g_vthi[BH_ * D_ * N_];               // [bh][d][n] (fp16 only)

__device__ __align__(128) __half g_atth[M_ * C_];   // attn out fp16 [M][C]

// ---------------------------------------------------------------------------
// helpers
// ---------------------------------------------------------------------------
__device__ __forceinline__ void mma16816(float* c, const uint32_t* a,
                                         uint32_t b0, uint32_t b1)
{
    asm volatile(
        "mma.sync.aligned.m16n8k16.row.col.f32.f16.f16.f32 "
        "{%0,%1,%2,%3}, {%4,%5,%6,%7}, {%8,%9}, {%0,%1,%2,%3};"
        : "+f"(c[0]), "+f"(c[1]), "+f"(c[2]), "+f"(c[3])
        : "r"(a[0]), "r"(a[1]), "r"(a[2]), "r"(a[3]), "r"(b0), "r"(b1));
}

__device__ __forceinline__ uint32_t packf16(float lo, float hi)
{
    uint32_t r;
    asm("cvt.rn.f16x2.f32 %0, %1, %2;" : "=r"(r) : "f"(hi), "f"(lo));
    return r;
}

__device__ __forceinline__ uint32_t ex2_f16x2(uint32_t a)
{
    uint32_t r;
    asm("ex2.approx.f16x2 %0, %1;" : "=r"(r) : "r"(a));
    return r;
}

__device__ __forceinline__ float ex2(float x)
{
    float y;
    asm("ex2.approx.f32 %0, %1;" : "=f"(y) : "f"(x));
    return y;
}

__device__ __forceinline__ float sum2_f16(uint32_t p)
{
    const float2 f = __half22float2(*(const __half2*)&p);
    return f.x + f.y;
}

__device__ __forceinline__ void cpa16(uint32_t s, const void* g)
{
    asm volatile("cp.async.cg.shared.global [%0], [%1], 16;" :: "r"(s), "l"(g));
}
__device__ __forceinline__ void cpa8(uint32_t s, const void* g)
{
    asm volatile("cp.async.ca.shared.global [%0], [%1], 8;" :: "r"(s), "l"(g));
}
#define CP_COMMIT() asm volatile("cp.async.commit_group;")
#define CP_WAIT0()  asm volatile("cp.async.wait_group 0;")

// ---------------------------------------------------------------------------
// Conversion kernels
// ---------------------------------------------------------------------------
__global__ __launch_bounds__(256)
void convert_x_kernel(const float* __restrict__ x)
{
    const int i = (blockIdx.x * 256 + threadIdx.x) * 4;
    float4 v = *(const float4*)&x[i];
    __half h0 = __float2half_rn(v.x), h1 = __float2half_rn(v.y);
    __half h2 = __float2half_rn(v.z), h3 = __float2half_rn(v.w);
    __half l0 = __float2half_rn(v.x - __half2float(h0));
    __half l1 = __float2half_rn(v.y - __half2float(h1));
    __half l2 = __float2half_rn(v.z - __half2float(h2));
    __half l3 = __float2half_rn(v.w - __half2float(h3));
    *(__half2*)&g_xh[i]     = __halves2half2(h0, h1);
    *(__half2*)&g_xh[i + 2] = __halves2half2(h2, h3);
    *(__half2*)&g_xl[i]     = __halves2half2(l0, l1);
    *(__half2*)&g_xl[i + 2] = __halves2half2(l2, l3);
}

// w [K][Nw] fp32 -> wt_hi/lo [Nw][K] half
__global__ __launch_bounds__(256)
void convert_w_kernel(const float* __restrict__ w, __half* __restrict__ wth,
                      __half* __restrict__ wtl, int K, int Nw)
{
    const int idx = blockIdx.x * 256 + threadIdx.x;  // = n*K + k
    const int n = idx / K, k = idx % K;
    const float v = w[(size_t)k * Nw + n];
    const __half hi = __float2half_rn(v);
    wth[idx] = hi;
    wtl[idx] = __float2half_rn(v - __half2float(hi));
}

// ---------------------------------------------------------------------------
// HMMA GEMM, 128x128 CTA tile: C[M,Nw] = A[M,256] @ B[256,Nw] + bias.
// BK=16, 8 warps (4m x 2n), warp tile 32x64.
// 2-stage cp.async double buffer, STATIC SMEM (48KB), 1 sync per iter.
// MODE 0: scatter to Q/K/V arrays (QKV GEMM, Nw=768).
//         V column-tiles (col0>=512) use single hi*hi MMA pass.
// MODE 1: proj GEMM, Nw=256. Uses A-hi only (ah*bh + ah*bl), fp32 out + bias.
// ---------------------------------------------------------------------------
#define ASTR2 24   // 16 + 8 pad halfs -> conflict-free fragment LDS

template <int MODE>
__global__ __launch_bounds__(256)
void hgemm_kernel(const __half* __restrict__ Ah, const __half* __restrict__ Al,
                  const __half* __restrict__ Bth, const __half* __restrict__ Btl,
                  const float* __restrict__ bias, float* __restrict__ Cout,
                  int Nw)
{
    __shared__ __align__(16) __half sA[2][2][128][ASTR2];  // [stage][hi/lo][row][k]  24KB
    __shared__ __align__(16) __half sB[2][2][128][ASTR2];  //                          24KB

    const int tid  = threadIdx.x;
    const int warp = tid >> 5;
    const int lane = tid & 31;
    const int g    = lane >> 2;
    const int t4   = lane & 3;
    const int m_base = (warp >> 1) * 32;
    const int n_base = (warp & 1) * 64;
    const int row0 = blockIdx.y * 128;
    const int col0 = blockIdx.x * 128;

    // MODE0 V tile: fp16-grade output -> hi*hi only. MODE1: no A-lo pass.
    const bool vtile   = (MODE == 0) && (col0 >= 512);
    const bool loadAlo = (MODE == 0) && !vtile;
    const bool loadBlo = (MODE == 1) || ((MODE == 0) && !vtile);

    // global load mappings (per 16-wide K slice): 128 rows x 16 cols, 8 halfs/thread
    const int ar = tid >> 1, ac = (tid & 1) * 8;
    const __half* pAh = Ah  + (size_t)(row0 + ar) * C_ + ac;
    const __half* pAl = Al  + (size_t)(row0 + ar) * C_ + ac;
    const __half* pBh = Bth + (size_t)(col0 + ar) * C_ + ac;
    const __half* pBl = Btl + (size_t)(col0 + ar) * C_ + ac;

    const uint32_t sAh_addr0 = (uint32_t)__cvta_generic_to_shared(&sA[0][0][ar][ac]);
    const uint32_t sAl_addr0 = (uint32_t)__cvta_generic_to_shared(&sA[0][1][ar][ac]);
    const uint32_t sBh_addr0 = (uint32_t)__cvta_generic_to_shared(&sB[0][0][ar][ac]);
    const uint32_t sBl_addr0 = (uint32_t)__cvta_generic_to_shared(&sB[0][1][ar][ac]);
    const uint32_t aStage = 2 * 128 * ASTR2 * 2;   // bytes per stage
    const uint32_t bStage = 2 * 128 * ASTR2 * 2;

    float acc[2][8][4];
#pragma unroll
    for (int mf = 0; mf < 2; mf++)
#pragma unroll
        for (int nf = 0; nf < 8; nf++)
#pragma unroll
            for (int i = 0; i < 4; i++) acc[mf][nf][i] = 0.f;

    // prologue: issue tile 0
    {
        cpa16(sAh_addr0, pAh);
        cpa16(sBh_addr0, pBh);
        if (loadAlo) cpa16(sAl_addr0, pAl);
        if (loadBlo) cpa16(sBl_addr0, pBl);
        CP_COMMIT();
    }

    for (int it = 0; it < C_ / 16; it++) {
        CP_WAIT0();
        __syncthreads();
        if (it + 1 < C_ / 16) {
            const int s = (it + 1) & 1;
            const int k0 = (it + 1) * 16;
            cpa16(sAh_addr0 + s * aStage, pAh + k0);
            cpa16(sBh_addr0 + s * bStage, pBh + k0);
            if (loadAlo) cpa16(sAl_addr0 + s * aStage, pAl + k0);
            if (loadBlo) cpa16(sBl_addr0 + s * bStage, pBl + k0);
            CP_COMMIT();
        }
        const int s = it & 1;

        uint32_t ah[2][4], al[2][4];
#pragma unroll
        for (int mf = 0; mf < 2; mf++) {
            const int r = m_base + mf * 16;
            ah[mf][0] = *(const uint32_t*)&sA[s][0][r + g][2 * t4];
            ah[mf][1] = *(const uint32_t*)&sA[s][0][r + g + 8][2 * t4];
            ah[mf][2] = *(const uint32_t*)&sA[s][0][r + g][2 * t4 + 8];
            ah[mf][3] = *(const uint32_t*)&sA[s][0][r + g + 8][2 * t4 + 8];
            if (loadAlo) {
                al[mf][0] = *(const uint32_t*)&sA[s][1][r + g][2 * t4];
                al[mf][1] = *(const uint32_t*)&sA[s][1][r + g + 8][2 * t4];
                al[mf][2] = *(const uint32_t*)&sA[s][1][r + g][2 * t4 + 8];
                al[mf][3] = *(const uint32_t*)&sA[s][1][r + g + 8][2 * t4 + 8];
            }
        }
#pragma unroll
        for (int nf = 0; nf < 8; nf++) {
            const int n = n_base + nf * 8 + g;
            const uint32_t bh0 = *(const uint32_t*)&sB[s][0][n][2 * t4];
            const uint32_t bh1 = *(const uint32_t*)&sB[s][0][n][2 * t4 + 8];
#pragma unroll
            for (int mf = 0; mf < 2; mf++)
                mma16816(acc[mf][nf], ah[mf], bh0, bh1);
            if (loadBlo) {
                const uint32_t bl0 = *(const uint32_t*)&sB[s][1][n][2 * t4];
                const uint32_t bl1 = *(const uint32_t*)&sB[s][1][n][2 * t4 + 8];
#pragma unroll
                for (int mf = 0; mf < 2; mf++)
                    mma16816(acc[mf][nf], ah[mf], bl0, bl1);
            }
            if (loadAlo) {
#pragma unroll
                for (int mf = 0; mf < 2; mf++)
                    mma16816(acc[mf][nf], al[mf], bh0, bh1);
            }
        }
    }

    // --- epilogue ---
#pragma unroll
    for (int mf = 0; mf < 2; mf++) {
#pragma unroll
        for (int nf = 0; nf < 8; nf++) {
#pragma unroll
            for (int ii = 0; ii < 2; ii++) {
                const int mrow = row0 + m_base + mf * 16 + g + ii * 8;
                const int ncol = col0 + n_base + nf * 8 + 2 * t4;
                float v0 = acc[mf][nf][ii * 2]     + bias[ncol];
                float v1 = acc[mf][nf][ii * 2 + 1] + bias[ncol + 1];
                if (MODE == 0) {
                    const int b = mrow >> 11, nn = mrow & 2047;
                    const int sSel = ncol >> 8, rem = ncol & 255;
                    const int h = rem >> 4, d = rem & 15;
                    const int bh = (b << 4) + h;
                    if (sSel == 0) { v0 *= L2E; v1 *= L2E; }
                    const __half h0 = __float2half_rn(v0);
                    const __half h1 = __float2half_rn(v1);
                    if (sSel == 2) {
                        g_vthi[((size_t)bh * D_ + d) * N_ + nn]     = h0;
                        g_vthi[((size_t)bh * D_ + d + 1) * N_ + nn] = h1;
                    } else {
                        const __half l0 = __float2half_rn(v0 - __half2float(h0));
                        const __half l1 = __float2half_rn(v1 - __half2float(h1));
                        const size_t idx = ((size_t)bh * N_ + nn) * D_ + d;
                        if (sSel == 0) {
                            *(__half2*)&g_qhi[idx] = __halves2half2(h0, h1);
                            *(__half2*)&g_qlo[idx] = __halves2half2(l0, l1);
                        } else {
                            *(__half2*)&g_khi[idx] = __halves2half2(h0, h1);
                            *(__half2*)&g_klo[idx] = __halves2half2(l0, l1);
                        }
                    }
                } else {
                    float2 o; o.x = v0; o.y = v1;
                    *(float2*)&Cout[(size_t)mrow * Nw + ncol] = o;
                }
            }
        }
    }
}

// ---------------------------------------------------------------------------
// FA2-style attention (unchanged math): 8 warps, 128 queries/CTA, 64-key tiles.
// QK hi/lo 3-pass, PV fp16 V, l on ALU pipe. Output: fp16 g_atth only.
// ---------------------------------------------------------------------------
#define KSTRIDE 24
#define VSTRIDE 72

__global__ __launch_bounds__(256)
void attn_mma_kernel()
{
    __shared__ __align__(16) __half sKh[2][64][KSTRIDE];
    __shared__ __align__(16) __half sKl[2][64][KSTRIDE];
    __shared__ __align__(16) __half sVh[2][16][VSTRIDE];

    const int tid  = threadIdx.x;
    const int warp = tid >> 5;
    const int lane = tid & 31;
    const int g    = lane >> 2;
    const int t4   = lane & 3;
    const int bh   = blockIdx.y;
    const int q0   = blockIdx.x * 128 + warp * 16;

    uint32_t qh[4], ql[4];
    {
        const __half* qb_hi = &g_qhi[((size_t)bh * N_ + q0) * D_];
        const __half* qb_lo = &g_qlo[((size_t)bh * N_ + q0) * D_];
        qh[0] = *(const uint32_t*)&qb_hi[(g)     * D_ + 2 * t4];
        qh[1] = *(const uint32_t*)&qb_hi[(g + 8) * D_ + 2 * t4];
        qh[2] = *(const uint32_t*)&qb_hi[(g)     * D_ + 2 * t4 + 8];
        qh[3] = *(const uint32_t*)&qb_hi[(g + 8) * D_ + 2 * t4 + 8];
        ql[0] = *(const uint32_t*)&qb_lo[(g)     * D_ + 2 * t4];
        ql[1] = *(const uint32_t*)&qb_lo[(g + 8) * D_ + 2 * t4];
        ql[2] = *(const uint32_t*)&qb_lo[(g)     * D_ + 2 * t4 + 8];
        ql[3] = *(const uint32_t*)&qb_lo[(g + 8) * D_ + 2 * t4 + 8];
    }

    float O[2][4];
#pragma unroll
    for (int dt = 0; dt < 2; dt++)
#pragma unroll
        for (int i = 0; i < 4; i++) O[dt][i] = 0.f;
    float l0 = 0.f, l1 = 0.f;
    float m0 = -1e30f, m1 = -1e30f;

    const int kk  = tid >> 2;
    const int kdg = (tid & 3) * 4;
    const int vd  = tid >> 4;
    const int vkg = (tid & 15) * 4;
    const __half* gk_hi = &g_khi[((size_t)bh * N_ + kk) * D_ + kdg];
    const __half* gk_lo = &g_klo[((size_t)bh * N_ + kk) * D_ + kdg];
    const __half* gv_hi = &g_vthi[((size_t)bh * D_ + vd) * N_ + vkg];

    const uint32_t aKh = (uint32_t)__cvta_generic_to_shared(&sKh[0][kk][kdg]);
    const uint32_t aKl = (uint32_t)__cvta_generic_to_shared(&sKl[0][kk][kdg]);
    const uint32_t aVh = (uint32_t)__cvta_generic_to_shared(&sVh[0][vd][vkg]);
    const uint32_t kStage = 64 * KSTRIDE * 2;
    const uint32_t vStage = 16 * VSTRIDE * 2;

    cpa8(aKh, gk_hi);
    cpa8(aKl, gk_lo);
    cpa8(aVh, gv_hi);
    CP_COMMIT();

    for (int kt = 0; kt < N_ / 64; kt++) {
        CP_WAIT0();
        __syncthreads();
        if (kt + 1 < N_ / 64) {
            const uint32_t s = (kt + 1) & 1;
            cpa8(aKh + s * kStage, gk_hi + (size_t)(kt + 1) * 64 * D_);
            cpa8(aKl + s * kStage, gk_lo + (size_t)(kt + 1) * 64 * D_);
            cpa8(aVh + s * vStage, gv_hi + (kt + 1) * 64);
            CP_COMMIT();
        }
        const int s = kt & 1;

        uint32_t kh0[8], kh1[8], kl0[8], kl1[8];
#pragma unroll
        for (int nt = 0; nt < 8; nt++) {
            const int key = nt * 8 + g;
            kh0[nt] = *(const uint32_t*)&sKh[s][key][2 * t4];
            kh1[nt] = *(const uint32_t*)&sKh[s][key][2 * t4 + 8];
            kl0[nt] = *(const uint32_t*)&sKl[s][key][2 * t4];
            kl1[nt] = *(const uint32_t*)&sKl[s][key][2 * t4 + 8];
        }

        float S[8][4];
#pragma unroll
        for (int nt = 0; nt < 8; nt++) {
#pragma unroll
            for (int i = 0; i < 4; i++) S[nt][i] = 0.f;
        }
#pragma unroll
        for (int nt = 0; nt < 8; nt++) mma16816(S[nt], qh, kh0[nt], kh1[nt]);
#pragma unroll
        for (int nt = 0; nt < 8; nt++) mma16816(S[nt], qh, kl0[nt], kl1[nt]);
#pragma unroll
        for (int nt = 0; nt < 8; nt++) mma16816(S[nt], ql, kh0[nt], kh1[nt]);

        float cm0 = m0, cm1 = m1;
#pragma unroll
        for (int nt = 0; nt < 8; nt++) {
            cm0 = fmaxf(cm0, fmaxf(S[nt][0], S[nt][1]));
            cm1 = fmaxf(cm1, fmaxf(S[nt][2], S[nt][3]));
        }
        cm0 = fmaxf(cm0, __shfl_xor_sync(0xffffffffu, cm0, 1));
        cm0 = fmaxf(cm0, __shfl_xor_sync(0xffffffffu, cm0, 2));
        cm1 = fmaxf(cm1, __shfl_xor_sync(0xffffffffu, cm1, 1));
        cm1 = fmaxf(cm1, __shfl_xor_sync(0xffffffffu, cm1, 2));

        const float corr0 = ex2(m0 - cm0);
        const float corr1 = ex2(m1 - cm1);
        m0 = cm0; m1 = cm1;
#pragma unroll
        for (int dt = 0; dt < 2; dt++) {
            O[dt][0] *= corr0; O[dt][1] *= corr0;
            O[dt][2] *= corr1; O[dt][3] *= corr1;
        }
        l0 *= corr0; l1 *= corr1;

        uint32_t P[4][4];
#pragma unroll
        for (int kt2 = 0; kt2 < 4; kt2++) {
            P[kt2][0] = ex2_f16x2(packf16(S[2 * kt2][0] - cm0,     S[2 * kt2][1] - cm0));
            P[kt2][1] = ex2_f16x2(packf16(S[2 * kt2][2] - cm1,     S[2 * kt2][3] - cm1));
            P[kt2][2] = ex2_f16x2(packf16(S[2 * kt2 + 1][0] - cm0, S[2 * kt2 + 1][1] - cm0));
            P[kt2][3] = ex2_f16x2(packf16(S[2 * kt2 + 1][2] - cm1, S[2 * kt2 + 1][3] - cm1));
        }

#pragma unroll
        for (int kt2 = 0; kt2 < 4; kt2++) {
            l0 += sum2_f16(P[kt2][0]) + sum2_f16(P[kt2][2]);
            l1 += sum2_f16(P[kt2][1]) + sum2_f16(P[kt2][3]);
        }

#pragma unroll
        for (int kt2 = 0; kt2 < 4; kt2++) {
#pragma unroll
            for (int dt = 0; dt < 2; dt++) {
                const int drow = dt * 8 + g;
                uint32_t vh0 = *(const uint32_t*)&sVh[s][drow][kt2 * 16 + 2 * t4];
                uint32_t vh1 = *(const uint32_t*)&sVh[s][drow][kt2 * 16 + 2 * t4 + 8];
                mma16816(O[dt], P[kt2], vh0, vh1);
            }
        }
    }

    float lf0 = l0, lf1 = l1;
    lf0 += __shfl_xor_sync(0xffffffffu, lf0, 1);
    lf0 += __shfl_xor_sync(0xffffffffu, lf0, 2);
    lf1 += __shfl_xor_sync(0xffffffffu, lf1, 1);
    lf1 += __shfl_xor_sync(0xffffffffu, lf1, 2);
    const float inv0 = 1.f / lf0;
    const float inv1 = 1.f / lf1;

    const int b = bh >> 4, h = bh & 15;
    const size_t r0 = ((size_t)(b * N_ + q0 + g))     * C_ + h * D_;
    const size_t r1 = ((size_t)(b * N_ + q0 + g + 8)) * C_ + h * D_;
#pragma unroll
    for (int dt = 0; dt < 2; dt++) {
        const float a0 = O[dt][0] * inv0, a1 = O[dt][1] * inv0;
        const float b0 = O[dt][2] * inv1, b1 = O[dt][3] * inv1;
        const size_t c = dt * 8 + 2 * t4;
        *(__half2*)&g_atth[r0 + c] =
            __halves2half2(__float2half_rn(a0), __float2half_rn(a1));
        *(__half2*)&g_atth[r1 + c] =
            __halves2half2(__float2half_rn(b0), __float2half_rn(b1));
    }
}

// ---------------------------------------------------------------------------
extern "C" void kernel_launch(void* const* d_in, const int* in_sizes, int n_in,
                              void* d_out, int out_size)
{
    const float* x      = (const float*)d_in[0];   // (B,N,C)
    const float* w_qkv  = (const float*)d_in[1];   // (C,3C)
    const float* b_qkv  = (const float*)d_in[2];   // (3C,)
    const float* w_proj = (const float*)d_in[3];   // (C,C)
    const float* b_proj = (const float*)d_in[4];   // (C,)
    float* out = (float*)d_out;

    __half *xh, *xl, *wqt_h, *wqt_l, *wpt_h, *wpt_l, *atth;
    cudaGetSymbolAddress((void**)&xh, g_xh);
    cudaGetSymbolAddress((void**)&xl, g_xl);
    cudaGetSymbolAddress((void**)&wqt_h, g_wqt_h);
    cudaGetSymbolAddress((void**)&wqt_l, g_wqt_l);
    cudaGetSymbolAddress((void**)&wpt_h, g_wpt_h);
    cudaGetSymbolAddress((void**)&wpt_l, g_wpt_l);
    cudaGetSymbolAddress((void**)&atth, g_atth);

    // 0) conversions
    convert_x_kernel<<<M_ * C_ / 4 / 256, 256>>>(x);
    convert_w_kernel<<<C_ * K3_ / 256, 256>>>(w_qkv, wqt_h, wqt_l, C_, K3_);
    convert_w_kernel<<<C_ * C_ / 256, 256>>>(w_proj, wpt_h, wpt_l, C_, C_);

    // 1) QKV GEMM (HMMA, 128x128 tiles) + scatter: (8192x256)@(256x768)
    {
        dim3 grid(K3_ / 128, M_ / 128);
        hgemm_kernel<0><<<grid, 256>>>(xh, xl, wqt_h, wqt_l, b_qkv, nullptr, K3_);
    }
    // 2) Attention (mma.sync tensor cores)
    {
        dim3 grid(N_ / 128, BH_);
        attn_mma_kernel<<<grid, 256>>>();
    }
    // 3) Output projection (HMMA, 128x128 tiles, A-hi only): (8192x256)@(256x256)
    {
        dim3 grid(C_ / 128, M_ / 128);
        hgemm_kernel<1><<<grid, 256>>>(atth, atth, wpt_h, wpt_l, b_proj, out, C_);
    }
}